// round 10
// baseline (speedup 1.0000x reference)
#include <cuda_runtime.h>
#include <cuda_bf16.h>
#include <math.h>

// Problem constants (fixed shapes for this problem)
#define NMAX 50000
#define EMAX 800000
#define HDIM 128

// ---------------------------------------------------------------------------
// Device scratch (static __device__ arrays; no allocation anywhere)
// ---------------------------------------------------------------------------
__device__ int   g_indeg[NMAX];
__device__ int   g_rowptr[NMAX + 1];
__device__ int   g_cursor[NMAX];
__device__ int   g_csr[EMAX];
__device__ float g_dinv[NMAX];
__device__ float g_t1[NMAX * HDIM];    // x @ W1
__device__ float g_h[NMAX * HDIM];     // relu(agg(t1)+b1)
__device__ float g_t2[NMAX * HDIM];    // h @ W2
__device__ float g_t2u[NMAX * HDIM];   // h @ W2u
__device__ float g_fu[NMAX * HDIM];    // feat_unlabel
__device__ float g_feat[NMAX * HDIM];  // feat = feat_label + feat_unlabel
__device__ float g_wt_pca[HDIM * HDIM];
__device__ float g_wt_bce[HDIM * HDIM];

// ---------------------------------------------------------------------------
// CSR build
// ---------------------------------------------------------------------------
__global__ void zero_kernel(int n) {
    int i = blockIdx.x * blockDim.x + threadIdx.x;
    if (i < n) { g_indeg[i] = 0; g_cursor[i] = 0; }
}

__global__ void hist_kernel(const int* __restrict__ ei, int e) {
    int i = blockIdx.x * blockDim.x + threadIdx.x;
    if (i < e) atomicAdd(&g_indeg[__ldg(ei + e + i)], 1);
}

__global__ void dinv_kernel(int n) {
    int i = blockIdx.x * blockDim.x + threadIdx.x;
    if (i < n) g_dinv[i] = rsqrtf((float)(g_indeg[i] + 1));  // +1 self loop
}

// single-block exclusive scan of indeg -> rowptr
__global__ void scan_kernel(int n) {
    __shared__ int sh[1024];
    int t = threadIdx.x;
    int chunk = (n + 1023) >> 10;
    int beg = t * chunk;
    int end = beg + chunk; if (end > n) end = n;
    int s = 0;
    for (int i = beg; i < end; i++) s += g_indeg[i];
    sh[t] = s;
    __syncthreads();
    // inclusive Hillis-Steele scan
    for (int off = 1; off < 1024; off <<= 1) {
        int v = (t >= off) ? sh[t - off] : 0;
        __syncthreads();
        sh[t] += v;
        __syncthreads();
    }
    int excl = (t == 0) ? 0 : sh[t - 1];
    for (int i = beg; i < end; i++) { g_rowptr[i] = excl; excl += g_indeg[i]; }
    if (t == 1023) g_rowptr[n] = sh[1023];
}

__global__ void scatter_kernel(const int* __restrict__ ei, int e) {
    int i = blockIdx.x * blockDim.x + threadIdx.x;
    if (i < e) {
        int s = __ldg(ei + i);
        int d = __ldg(ei + e + i);
        int pos = atomicAdd(&g_cursor[d], 1);
        g_csr[g_rowptr[d] + pos] = s;
    }
}

// ---------------------------------------------------------------------------
// GEMM: C[M,128] = A[M,128] @ B[128,128] (+bias). fp32, tiled 128x128x16.
// 256 threads; each computes an 8x8 register tile. 8 k0-steps, 16 barriers.
// ---------------------------------------------------------------------------
#define KT 16

template <bool BIAS>
__global__ __launch_bounds__(256, 2)
void gemm128(const float* __restrict__ A, const float* __restrict__ B,
             const float* __restrict__ bias, float* __restrict__ C, int M) {
    __shared__ float As[KT][HDIM];  // transposed A tile: As[k][m]
    __shared__ float Bs[KT][HDIM];
    int tid = threadIdx.x;
    int m0  = blockIdx.x * 128;
    int tx  = tid & 15;   // 0..15, output col group
    int ty  = tid >> 4;   // 0..15, output row group

    float acc[8][8];
#pragma unroll
    for (int i = 0; i < 8; i++)
#pragma unroll
        for (int j = 0; j < 8; j++) acc[i][j] = 0.f;

    // A tile load: 128 rows x 16 cols = 512 float4; thread loads 2 float4
    int rowA = tid >> 1;           // 0..127
    int colA = (tid & 1) * 8;      // 0 / 8 (two float4 = 8 floats)
    // B tile load: 16 rows x 128 cols = 512 float4; thread loads 2 float4
    int rowB = tid >> 4;           // 0..15
    int colB = (tid & 15) * 8;     // 0..120
    bool aok = (m0 + rowA) < M;
    const float* Arow = A + (size_t)(m0 + rowA) * HDIM;

    for (int k0 = 0; k0 < HDIM; k0 += KT) {
        float4 a0, a1;
        if (aok) {
            a0 = *(const float4*)(Arow + k0 + colA);
            a1 = *(const float4*)(Arow + k0 + colA + 4);
        } else {
            a0 = make_float4(0.f, 0.f, 0.f, 0.f);
            a1 = a0;
        }
        float4 b0 = *(const float4*)(B + (size_t)(k0 + rowB) * HDIM + colB);
        float4 b1 = *(const float4*)(B + (size_t)(k0 + rowB) * HDIM + colB + 4);
        As[colA + 0][rowA] = a0.x;
        As[colA + 1][rowA] = a0.y;
        As[colA + 2][rowA] = a0.z;
        As[colA + 3][rowA] = a0.w;
        As[colA + 4][rowA] = a1.x;
        As[colA + 5][rowA] = a1.y;
        As[colA + 6][rowA] = a1.z;
        As[colA + 7][rowA] = a1.w;
        *(float4*)&Bs[rowB][colB]     = b0;
        *(float4*)&Bs[rowB][colB + 4] = b1;
        __syncthreads();
#pragma unroll
        for (int k = 0; k < KT; k++) {
            float rm[8], rn[8];
#pragma unroll
            for (int i = 0; i < 8; i++) rm[i] = As[k][ty * 8 + i];
#pragma unroll
            for (int j = 0; j < 8; j++) rn[j] = Bs[k][tx * 8 + j];
#pragma unroll
            for (int i = 0; i < 8; i++)
#pragma unroll
                for (int j = 0; j < 8; j++) acc[i][j] += rm[i] * rn[j];
        }
        __syncthreads();
    }

#pragma unroll
    for (int i = 0; i < 8; i++) {
        int m = m0 + ty * 8 + i;
        if (m >= M) break;
        float* crow = C + (size_t)m * HDIM + tx * 8;
#pragma unroll
        for (int j4 = 0; j4 < 2; j4++) {
            float4 v;
            int c = tx * 8 + j4 * 4;
            v.x = acc[i][j4 * 4 + 0];
            v.y = acc[i][j4 * 4 + 1];
            v.z = acc[i][j4 * 4 + 2];
            v.w = acc[i][j4 * 4 + 3];
            if (BIAS) {
                v.x += bias[c + 0]; v.y += bias[c + 1];
                v.z += bias[c + 2]; v.w += bias[c + 3];
            }
            *(float4*)(crow + j4 * 4) = v;
        }
    }
}

// ---------------------------------------------------------------------------
// Aggregation: out[v] = dinv[v]*sum_{e:s->v} t[s]*dinv[s] + t[v]*dinv[v]^2 + b
// one block (128 thr) per node; thread f owns feature f -> coalesced gathers
// ---------------------------------------------------------------------------
__global__ void agg1_kernel(const float* __restrict__ t, const float* __restrict__ b,
                            float* __restrict__ out) {
    int v = blockIdx.x;
    int f = threadIdx.x;
    int beg = g_rowptr[v], end = g_rowptr[v + 1];
    float acc = 0.f;
    int idx = beg;
    for (; idx + 3 < end; idx += 4) {
        int s0 = g_csr[idx], s1 = g_csr[idx + 1], s2 = g_csr[idx + 2], s3 = g_csr[idx + 3];
        float w0 = g_dinv[s0], w1 = g_dinv[s1], w2 = g_dinv[s2], w3 = g_dinv[s3];
        float v0 = __ldg(t + (size_t)s0 * HDIM + f);
        float v1 = __ldg(t + (size_t)s1 * HDIM + f);
        float v2 = __ldg(t + (size_t)s2 * HDIM + f);
        float v3 = __ldg(t + (size_t)s3 * HDIM + f);
        acc += v0 * w0 + v1 * w1 + v2 * w2 + v3 * w3;
    }
    for (; idx < end; ++idx) {
        int s = g_csr[idx];
        acc += __ldg(t + (size_t)s * HDIM + f) * g_dinv[s];
    }
    float dv = g_dinv[v];
    float r = dv * acc + __ldg(t + (size_t)v * HDIM + f) * dv * dv + b[f];
    out[(size_t)v * HDIM + f] = fmaxf(r, 0.f);  // relu (conv1 only)
}

// dual aggregation for conv2 / conv2u; writes feat_label, feat_unlabel, feat
__global__ void agg2_kernel(const float* __restrict__ b2, const float* __restrict__ b2u,
                            float* __restrict__ feat_label) {
    int v = blockIdx.x;
    int f = threadIdx.x;
    int beg = g_rowptr[v], end = g_rowptr[v + 1];
    float acc1 = 0.f, acc2 = 0.f;
    int idx = beg;
    for (; idx + 1 < end; idx += 2) {
        int s0 = g_csr[idx], s1 = g_csr[idx + 1];
        float w0 = g_dinv[s0], w1 = g_dinv[s1];
        float a0 = __ldg(g_t2  + (size_t)s0 * HDIM + f);
        float a1 = __ldg(g_t2  + (size_t)s1 * HDIM + f);
        float u0 = __ldg(g_t2u + (size_t)s0 * HDIM + f);
        float u1 = __ldg(g_t2u + (size_t)s1 * HDIM + f);
        acc1 += a0 * w0 + a1 * w1;
        acc2 += u0 * w0 + u1 * w1;
    }
    for (; idx < end; ++idx) {
        int s = g_csr[idx];
        float w = g_dinv[s];
        acc1 += __ldg(g_t2  + (size_t)s * HDIM + f) * w;
        acc2 += __ldg(g_t2u + (size_t)s * HDIM + f) * w;
    }
    float dv = g_dinv[v];
    float self = dv * dv;
    float fl = dv * acc1 + g_t2 [(size_t)v * HDIM + f] * self + b2[f];
    float fu = dv * acc2 + g_t2u[(size_t)v * HDIM + f] * self + b2u[f];
    feat_label[(size_t)v * HDIM + f] = fl;
    g_fu  [(size_t)v * HDIM + f] = fu;
    g_feat[(size_t)v * HDIM + f] = fl + fu;
}

// ---------------------------------------------------------------------------
// Head 1: out1 = ((feat_label / max(||fl||,1e-12)) @ Wh1^T + bh1) / 0.1
// one warp per node
// ---------------------------------------------------------------------------
__global__ void head1_kernel(const float* __restrict__ fl, const float* __restrict__ Wh1,
                             const float* __restrict__ bh1, float* __restrict__ out1, int n) {
    int warp = (blockIdx.x * blockDim.x + threadIdx.x) >> 5;
    int lane = threadIdx.x & 31;
    if (warp >= n) return;
    float4 x = *(const float4*)(fl + (size_t)warp * HDIM + lane * 4);
    float ss = x.x * x.x + x.y * x.y + x.z * x.z + x.w * x.w;
#pragma unroll
    for (int o = 16; o; o >>= 1) ss += __shfl_xor_sync(0xffffffffu, ss, o);
    float nrm = fmaxf(sqrtf(ss), 1e-12f);
    float inv = 10.f / nrm;  // divide by nrm then /0.1
    float res[4];
#pragma unroll
    for (int c = 0; c < 4; c++) {
        float4 w = *(const float4*)(Wh1 + c * HDIM + lane * 4);
        float d = x.x * w.x + x.y * w.y + x.z * w.z + x.w * w.w;
#pragma unroll
        for (int o = 16; o; o >>= 1) d += __shfl_xor_sync(0xffffffffu, d, o);
        res[c] = d * inv + bh1[c] * 10.f;
    }
    if (lane == 0) {
        float4 o;
        o.x = res[0]; o.y = res[1]; o.z = res[2]; o.w = res[3];
        *(float4*)(out1 + (size_t)warp * 4) = o;
    }
}

// tiny transpose for the head weight matrices (torch y = x @ W^T)
__global__ void transpose_kernel(const float* __restrict__ W, float* __restrict__ Wt) {
    int i = blockIdx.x * blockDim.x + threadIdx.x;  // 16384
    if (i < HDIM * HDIM) {
        int r = i >> 7, c = i & 127;
        Wt[i] = W[c * HDIM + r];
    }
}

// ---------------------------------------------------------------------------
// Launch
// ---------------------------------------------------------------------------
extern "C" void kernel_launch(void* const* d_in, const int* in_sizes, int n_in,
                              void* d_out, int out_size) {
    const float* x    = (const float*)d_in[0];
    const int*   ei   = (const int*)  d_in[1];
    const float* W1   = (const float*)d_in[2];
    const float* b1   = (const float*)d_in[3];
    const float* W2   = (const float*)d_in[4];
    const float* b2   = (const float*)d_in[5];
    const float* W2u  = (const float*)d_in[6];
    const float* b2u  = (const float*)d_in[7];
    const float* Wh1  = (const float*)d_in[8];
    const float* bh1  = (const float*)d_in[9];
    const float* Wpca = (const float*)d_in[10];
    const float* bpca = (const float*)d_in[11];
    const float* Wbce = (const float*)d_in[12];
    const float* bbce = (const float*)d_in[13];

    int n = in_sizes[0] / HDIM;
    int e = in_sizes[1] / 2;

    float* out     = (float*)d_out;
    float* out1    = out;                          // [n,4]
    float* out_pca = out + (size_t)n * 4;          // [n,128]
    float* out_bce = out_pca + (size_t)n * HDIM;   // [n,128]
    float* out_fl  = out_bce + (size_t)n * HDIM;   // [n,128] feat_label

    // scratch pointers via symbols (host-side query; capture-legal)
    float *t1, *h, *t2, *t2u, *fu, *feat, *wtp, *wtb;
    cudaGetSymbolAddress((void**)&t1,   g_t1);
    cudaGetSymbolAddress((void**)&h,    g_h);
    cudaGetSymbolAddress((void**)&t2,   g_t2);
    cudaGetSymbolAddress((void**)&t2u,  g_t2u);
    cudaGetSymbolAddress((void**)&fu,   g_fu);
    cudaGetSymbolAddress((void**)&feat, g_feat);
    cudaGetSymbolAddress((void**)&wtp,  g_wt_pca);
    cudaGetSymbolAddress((void**)&wtb,  g_wt_bce);

    int nb256 = (n + 255) / 256;
    int eb256 = (e + 255) / 256;
    int gemm_grid = (n + 127) / 128;

    // ---- CSR build ----
    zero_kernel<<<nb256, 256>>>(n);
    hist_kernel<<<eb256, 256>>>(ei, e);
    dinv_kernel<<<nb256, 256>>>(n);
    scan_kernel<<<1, 1024>>>(n);
    scatter_kernel<<<eb256, 256>>>(ei, e);

    // ---- head-weight transposes (cheap, once per launch) ----
    transpose_kernel<<<64, 256>>>(Wpca, wtp);
    transpose_kernel<<<64, 256>>>(Wbce, wtb);

    // ---- conv1: h = relu(Agg(x@W1) + b1) ----
    gemm128<false><<<gemm_grid, 256>>>(x, W1, nullptr, t1, n);
    agg1_kernel<<<n, HDIM>>>(t1, b1, h);

    // ---- conv2 / conv2u ----
    gemm128<false><<<gemm_grid, 256>>>(h, W2,  nullptr, t2,  n);
    gemm128<false><<<gemm_grid, 256>>>(h, W2u, nullptr, t2u, n);
    agg2_kernel<<<n, HDIM>>>(b2, b2u, out_fl);

    // ---- heads ----
    head1_kernel<<<(n * 32 + 255) / 256, 256>>>(out_fl, Wh1, bh1, out1, n);
    gemm128<true><<<gemm_grid, 256>>>(feat, wtp, bpca, out_pca, n);
    gemm128<true><<<gemm_grid, 256>>>(fu,   wtb, bbce, out_bce, n);
}

// round 17
// speedup vs baseline: 1.4859x; 1.4859x over previous
#include <cuda_runtime.h>
#include <cuda_bf16.h>
#include <math.h>

// Problem constants (fixed shapes for this problem)
#define NMAX 50000
#define EMAX 800000
#define HDIM 128
#define SBS  512   // scan block size
#define MAXSB 128  // max scan blocks (ceil(50000/512)=98)

// ---------------------------------------------------------------------------
// Device scratch (static __device__ arrays; no allocation anywhere)
// ---------------------------------------------------------------------------
__device__ int   g_indeg[NMAX];
__device__ int   g_rowptr[NMAX + 1];
__device__ int   g_cursor[NMAX];
__device__ int   g_csr[EMAX];
__device__ int   g_blocksum[MAXSB];
__device__ float g_dinv[NMAX];
__device__ float g_t1[NMAX * HDIM];    // x @ W1
__device__ float g_h[NMAX * HDIM];     // relu(agg(t1)+b1)
__device__ float g_t2[NMAX * HDIM];    // h @ W2
__device__ float g_t2u[NMAX * HDIM];   // h @ W2u
__device__ float g_fu[NMAX * HDIM];    // feat_unlabel
__device__ float g_feat[NMAX * HDIM];  // feat = feat_label + feat_unlabel
__device__ float g_wt_pca[HDIM * HDIM];
__device__ float g_wt_bce[HDIM * HDIM];

// ---------------------------------------------------------------------------
// CSR build
// ---------------------------------------------------------------------------
__global__ void zero_kernel(int n) {
    int i = blockIdx.x * blockDim.x + threadIdx.x;
    if (i < n) { g_indeg[i] = 0; g_cursor[i] = 0; }
}

__global__ void hist_kernel(const int* __restrict__ ei, int e) {
    int i = blockIdx.x * blockDim.x + threadIdx.x;
    if (i < e) atomicAdd(&g_indeg[__ldg(ei + e + i)], 1);
}

__global__ void dinv_kernel(int n) {
    int i = blockIdx.x * blockDim.x + threadIdx.x;
    if (i < n) g_dinv[i] = rsqrtf((float)(g_indeg[i] + 1));  // +1 self loop
}

// ---- multi-block exclusive scan of indeg -> rowptr (3 phases) ----
__global__ void scan1_kernel(int n) {
    __shared__ int sh[SBS];
    int t = threadIdx.x;
    int i = blockIdx.x * SBS + t;
    sh[t] = (i < n) ? g_indeg[i] : 0;
    __syncthreads();
#pragma unroll
    for (int off = SBS / 2; off > 0; off >>= 1) {
        if (t < off) sh[t] += sh[t + off];
        __syncthreads();
    }
    if (t == 0) g_blocksum[blockIdx.x] = sh[0];
}

__global__ void scan2_kernel(int nb) {
    __shared__ int sh[MAXSB];
    int t = threadIdx.x;  // 128 threads
    sh[t] = (t < nb) ? g_blocksum[t] : 0;
    __syncthreads();
#pragma unroll
    for (int off = 1; off < MAXSB; off <<= 1) {
        int v = (t >= off) ? sh[t - off] : 0;
        __syncthreads();
        sh[t] += v;
        __syncthreads();
    }
    if (t < nb) g_blocksum[t] = (t == 0) ? 0 : sh[t - 1];
}

__global__ void scan3_kernel(int n) {
    __shared__ int sh[SBS];
    int t = threadIdx.x;
    int i = blockIdx.x * SBS + t;
    int val = (i < n) ? g_indeg[i] : 0;
    sh[t] = val;
    __syncthreads();
#pragma unroll
    for (int off = 1; off < SBS; off <<= 1) {
        int v = (t >= off) ? sh[t - off] : 0;
        __syncthreads();
        sh[t] += v;
        __syncthreads();
    }
    int excl = sh[t] - val + g_blocksum[blockIdx.x];
    if (i < n) g_rowptr[i] = excl;
    if (i == n - 1) g_rowptr[n] = excl + val;
}

__global__ void scatter_kernel(const int* __restrict__ ei, int e) {
    int i = blockIdx.x * blockDim.x + threadIdx.x;
    if (i < e) {
        int s = __ldg(ei + i);
        int d = __ldg(ei + e + i);
        int pos = atomicAdd(&g_cursor[d], 1);
        g_csr[g_rowptr[d] + pos] = s;
    }
}

// ---------------------------------------------------------------------------
// TF32 GEMM: C[M,128] = A[M,128] @ B[128,128] (+bias), fp32 accumulate.
// 256 thr / 8 warps; CTA tile 128x128; warp tile 32x64; mma.m16n8k8.
// As[m][36] (pad->banks 4g+t4 all distinct), Bs[k][136] (banks 8t4+g distinct).
// ---------------------------------------------------------------------------
#define AST 36    // As row stride (floats)
#define BST 136   // Bs row stride (floats)
#define GKT 32    // k-chunk

__device__ __forceinline__ unsigned f2tf32(float x) {
    unsigned u;
    asm("cvt.rna.tf32.f32 %0, %1;" : "=r"(u) : "f"(x));
    return u;
}

__device__ __forceinline__ void mma_tf32(float* c, const unsigned* a,
                                         unsigned b0, unsigned b1) {
    asm volatile(
        "mma.sync.aligned.m16n8k8.row.col.f32.tf32.tf32.f32 "
        "{%0,%1,%2,%3}, {%4,%5,%6,%7}, {%8,%9}, {%0,%1,%2,%3};\n"
        : "+f"(c[0]), "+f"(c[1]), "+f"(c[2]), "+f"(c[3])
        : "r"(a[0]), "r"(a[1]), "r"(a[2]), "r"(a[3]), "r"(b0), "r"(b1));
}

template <bool BIAS>
__global__ __launch_bounds__(256, 2)
void gemm128(const float* __restrict__ A, const float* __restrict__ B,
             const float* __restrict__ bias, float* __restrict__ C, int M) {
    __shared__ unsigned As[128 * AST];
    __shared__ unsigned Bs[GKT * BST];
    int tid  = threadIdx.x;
    int m0   = blockIdx.x * 128;
    int warp = tid >> 5;
    int lane = tid & 31;
    int g    = lane >> 2;   // group id 0..7
    int t4   = lane & 3;    // thread-in-group 0..3
    int warp_m = (warp >> 1) * 32;
    int warp_n = (warp & 1) * 64;

    float c[2][8][4];
#pragma unroll
    for (int mt = 0; mt < 2; mt++)
#pragma unroll
        for (int nt = 0; nt < 8; nt++)
#pragma unroll
            for (int r = 0; r < 4; r++) c[mt][nt][r] = 0.f;

    // fill indices
    int arow = tid >> 1;               // 0..127
    int acol = (tid & 1) * 16;         // 0 / 16
    bool aok = (m0 + arow) < M;
    int brow = tid >> 3;               // 0..31
    int bcol = (tid & 7) * 16;         // 0..112

    for (int k0 = 0; k0 < HDIM; k0 += GKT) {
        // A tile: 128 x 32 -> As[m][k], tf32-converted
#pragma unroll
        for (int j = 0; j < 4; j++) {
            float4 v = aok ? *(const float4*)(A + (size_t)(m0 + arow) * HDIM + k0 + acol + j * 4)
                           : make_float4(0.f, 0.f, 0.f, 0.f);
            unsigned* dst = &As[arow * AST + acol + j * 4];
            dst[0] = f2tf32(v.x); dst[1] = f2tf32(v.y);
            dst[2] = f2tf32(v.z); dst[3] = f2tf32(v.w);
        }
        // B tile: 32 x 128 -> Bs[k][n], tf32-converted
#pragma unroll
        for (int j = 0; j < 4; j++) {
            float4 v = *(const float4*)(B + (size_t)(k0 + brow) * HDIM + bcol + j * 4);
            unsigned* dst = &Bs[brow * BST + bcol + j * 4];
            dst[0] = f2tf32(v.x); dst[1] = f2tf32(v.y);
            dst[2] = f2tf32(v.z); dst[3] = f2tf32(v.w);
        }
        __syncthreads();

#pragma unroll
        for (int kk = 0; kk < GKT; kk += 8) {
            unsigned a[2][4];
#pragma unroll
            for (int mt = 0; mt < 2; mt++) {
                int base = (warp_m + mt * 16 + g) * AST + kk + t4;
                a[mt][0] = As[base];
                a[mt][1] = As[base + 8 * AST];
                a[mt][2] = As[base + 4];
                a[mt][3] = As[base + 8 * AST + 4];
            }
#pragma unroll
            for (int nt = 0; nt < 8; nt++) {
                int bb = (kk + t4) * BST + warp_n + nt * 8 + g;
                unsigned b0 = Bs[bb];
                unsigned b1 = Bs[bb + 4 * BST];
                mma_tf32(c[0][nt], a[0], b0, b1);
                mma_tf32(c[1][nt], a[1], b0, b1);
            }
        }
        __syncthreads();
    }

    // store: c0/c1 -> (row0, col..col+1), c2/c3 -> (row0+8, ...)
#pragma unroll
    for (int mt = 0; mt < 2; mt++) {
        int row0 = m0 + warp_m + mt * 16 + g;
        int row1 = row0 + 8;
#pragma unroll
        for (int nt = 0; nt < 8; nt++) {
            int col = warp_n + nt * 8 + t4 * 2;
            float bx = 0.f, by = 0.f;
            if (BIAS) { bx = __ldg(bias + col); by = __ldg(bias + col + 1); }
            if (row0 < M) {
                float2 v0 = make_float2(c[mt][nt][0] + bx, c[mt][nt][1] + by);
                *(float2*)(C + (size_t)row0 * HDIM + col) = v0;
            }
            if (row1 < M) {
                float2 v1 = make_float2(c[mt][nt][2] + bx, c[mt][nt][3] + by);
                *(float2*)(C + (size_t)row1 * HDIM + col) = v1;
            }
        }
    }
}

// ---------------------------------------------------------------------------
// Aggregation: out[v] = dinv[v]*sum_{e:s->v} t[s]*dinv[s] + t[v]*dinv[v]^2 + b
// ---------------------------------------------------------------------------
__global__ void agg1_kernel(const float* __restrict__ t, const float* __restrict__ b,
                            float* __restrict__ out) {
    int v = blockIdx.x;
    int f = threadIdx.x;
    int beg = g_rowptr[v], end = g_rowptr[v + 1];
    float acc = 0.f;
    int idx = beg;
    for (; idx + 3 < end; idx += 4) {
        int s0 = g_csr[idx], s1 = g_csr[idx + 1], s2 = g_csr[idx + 2], s3 = g_csr[idx + 3];
        float w0 = g_dinv[s0], w1 = g_dinv[s1], w2 = g_dinv[s2], w3 = g_dinv[s3];
        float v0 = __ldg(t + (size_t)s0 * HDIM + f);
        float v1 = __ldg(t + (size_t)s1 * HDIM + f);
        float v2 = __ldg(t + (size_t)s2 * HDIM + f);
        float v3 = __ldg(t + (size_t)s3 * HDIM + f);
        acc += v0 * w0 + v1 * w1 + v2 * w2 + v3 * w3;
    }
    for (; idx < end; ++idx) {
        int s = g_csr[idx];
        acc += __ldg(t + (size_t)s * HDIM + f) * g_dinv[s];
    }
    float dv = g_dinv[v];
    float r = dv * acc + __ldg(t + (size_t)v * HDIM + f) * dv * dv + b[f];
    out[(size_t)v * HDIM + f] = fmaxf(r, 0.f);  // relu (conv1 only)
}

__global__ void agg2_kernel(const float* __restrict__ b2, const float* __restrict__ b2u,
                            float* __restrict__ feat_label) {
    int v = blockIdx.x;
    int f = threadIdx.x;
    int beg = g_rowptr[v], end = g_rowptr[v + 1];
    float acc1 = 0.f, acc2 = 0.f;
    int idx = beg;
    for (; idx + 1 < end; idx += 2) {
        int s0 = g_csr[idx], s1 = g_csr[idx + 1];
        float w0 = g_dinv[s0], w1 = g_dinv[s1];
        float a0 = __ldg(g_t2  + (size_t)s0 * HDIM + f);
        float a1 = __ldg(g_t2  + (size_t)s1 * HDIM + f);
        float u0 = __ldg(g_t2u + (size_t)s0 * HDIM + f);
        float u1 = __ldg(g_t2u + (size_t)s1 * HDIM + f);
        acc1 += a0 * w0 + a1 * w1;
        acc2 += u0 * w0 + u1 * w1;
    }
    for (; idx < end; ++idx) {
        int s = g_csr[idx];
        float w = g_dinv[s];
        acc1 += __ldg(g_t2  + (size_t)s * HDIM + f) * w;
        acc2 += __ldg(g_t2u + (size_t)s * HDIM + f) * w;
    }
    float dv = g_dinv[v];
    float self = dv * dv;
    float fl = dv * acc1 + g_t2 [(size_t)v * HDIM + f] * self + b2[f];
    float fu = dv * acc2 + g_t2u[(size_t)v * HDIM + f] * self + b2u[f];
    feat_label[(size_t)v * HDIM + f] = fl;
    g_fu  [(size_t)v * HDIM + f] = fu;
    g_feat[(size_t)v * HDIM + f] = fl + fu;
}

// ---------------------------------------------------------------------------
// Head 1: out1 = ((feat_label / max(||fl||,1e-12)) @ Wh1^T + bh1) / 0.1
// ---------------------------------------------------------------------------
__global__ void head1_kernel(const float* __restrict__ fl, const float* __restrict__ Wh1,
                             const float* __restrict__ bh1, float* __restrict__ out1, int n) {
    int warp = (blockIdx.x * blockDim.x + threadIdx.x) >> 5;
    int lane = threadIdx.x & 31;
    if (warp >= n) return;
    float4 x = *(const float4*)(fl + (size_t)warp * HDIM + lane * 4);
    float ss = x.x * x.x + x.y * x.y + x.z * x.z + x.w * x.w;
#pragma unroll
    for (int o = 16; o; o >>= 1) ss += __shfl_xor_sync(0xffffffffu, ss, o);
    float nrm = fmaxf(sqrtf(ss), 1e-12f);
    float inv = 10.f / nrm;
    float res[4];
#pragma unroll
    for (int c = 0; c < 4; c++) {
        float4 w = *(const float4*)(Wh1 + c * HDIM + lane * 4);
        float d = x.x * w.x + x.y * w.y + x.z * w.z + x.w * w.w;
#pragma unroll
        for (int o = 16; o; o >>= 1) d += __shfl_xor_sync(0xffffffffu, d, o);
        res[c] = d * inv + bh1[c] * 10.f;
    }
    if (lane == 0) {
        float4 o;
        o.x = res[0]; o.y = res[1]; o.z = res[2]; o.w = res[3];
        *(float4*)(out1 + (size_t)warp * 4) = o;
    }
}

// tiny transpose for the head weight matrices (torch y = x @ W^T)
__global__ void transpose_kernel(const float* __restrict__ W, float* __restrict__ Wt) {
    int i = blockIdx.x * blockDim.x + threadIdx.x;  // 16384
    if (i < HDIM * HDIM) {
        int r = i >> 7, c = i & 127;
        Wt[i] = W[c * HDIM + r];
    }
}

// ---------------------------------------------------------------------------
// Launch
// ---------------------------------------------------------------------------
extern "C" void kernel_launch(void* const* d_in, const int* in_sizes, int n_in,
                              void* d_out, int out_size) {
    const float* x    = (const float*)d_in[0];
    const int*   ei   = (const int*)  d_in[1];
    const float* W1   = (const float*)d_in[2];
    const float* b1   = (const float*)d_in[3];
    const float* W2   = (const float*)d_in[4];
    const float* b2   = (const float*)d_in[5];
    const float* W2u  = (const float*)d_in[6];
    const float* b2u  = (const float*)d_in[7];
    const float* Wh1  = (const float*)d_in[8];
    const float* bh1  = (const float*)d_in[9];
    const float* Wpca = (const float*)d_in[10];
    const float* bpca = (const float*)d_in[11];
    const float* Wbce = (const float*)d_in[12];
    const float* bbce = (const float*)d_in[13];

    int n = in_sizes[0] / HDIM;
    int e = in_sizes[1] / 2;

    float* out     = (float*)d_out;
    float* out1    = out;                          // [n,4]
    float* out_pca = out + (size_t)n * 4;          // [n,128]
    float* out_bce = out_pca + (size_t)n * HDIM;   // [n,128]
    float* out_fl  = out_bce + (size_t)n * HDIM;   // [n,128] feat_label

    float *t1, *h, *t2, *t2u, *fu, *feat, *wtp, *wtb;
    cudaGetSymbolAddress((void**)&t1,   g_t1);
    cudaGetSymbolAddress((void**)&h,    g_h);
    cudaGetSymbolAddress((void**)&t2,   g_t2);
    cudaGetSymbolAddress((void**)&t2u,  g_t2u);
    cudaGetSymbolAddress((void**)&fu,   g_fu);
    cudaGetSymbolAddress((void**)&feat, g_feat);
    cudaGetSymbolAddress((void**)&wtp,  g_wt_pca);
    cudaGetSymbolAddress((void**)&wtb,  g_wt_bce);

    int nb256 = (n + 255) / 256;
    int eb256 = (e + 255) / 256;
    int gemm_grid = (n + 127) / 128;
    int scan_blocks = (n + SBS - 1) / SBS;  // 98 for n=50000

    // ---- CSR build ----
    zero_kernel<<<nb256, 256>>>(n);
    hist_kernel<<<eb256, 256>>>(ei, e);
    dinv_kernel<<<nb256, 256>>>(n);
    scan1_kernel<<<scan_blocks, SBS>>>(n);
    scan2_kernel<<<1, MAXSB>>>(scan_blocks);
    scan3_kernel<<<scan_blocks, SBS>>>(n);
    scatter_kernel<<<eb256, 256>>>(ei, e);

    // ---- head-weight transposes ----
    transpose_kernel<<<64, 256>>>(Wpca, wtp);
    transpose_kernel<<<64, 256>>>(Wbce, wtb);

    // ---- conv1: h = relu(Agg(x@W1) + b1) ----
    gemm128<false><<<gemm_grid, 256>>>(x, W1, nullptr, t1, n);
    agg1_kernel<<<n, HDIM>>>(t1, b1, h);

    // ---- conv2 / conv2u ----
    gemm128<false><<<gemm_grid, 256>>>(h, W2,  nullptr, t2,  n);
    gemm128<false><<<gemm_grid, 256>>>(h, W2u, nullptr, t2u, n);
    agg2_kernel<<<n, HDIM>>>(b2, b2u, out_fl);

    // ---- heads ----
    head1_kernel<<<(n * 32 + 255) / 256, 256>>>(out_fl, Wh1, bh1, out1, n);
    gemm128<true><<<gemm_grid, 256>>>(feat, wtp, bpca, out_pca, n);
    gemm128<true><<<gemm_grid, 256>>>(fu,   wtb, bbce, out_bce, n);
}